// round 3
// baseline (speedup 1.0000x reference)
#include <cuda_runtime.h>
#include <cstdint>
#include <climits>

#define BDIM 512
constexpr int Bn = 16, Nn = 2000, Hh = 512, Ww = 512, MAXD = 10, TOPK_ = 5;
constexpr float CONF = 0.2f, IOUT = 0.4f;

// Scratch (device globals, allocation-free)
__device__ int g_bi[Bn][MAXD][4];
__device__ int g_k2[Bn][MAXD];

__device__ __forceinline__ float iou_f(float ax1, float ay1, float ax2, float ay2,
                                       float bx1, float by1, float bx2, float by2) {
    float aA = fmaxf(ax2 - ax1, 0.f) * fmaxf(ay2 - ay1, 0.f);
    float aB = fmaxf(bx2 - bx1, 0.f) * fmaxf(by2 - by1, 0.f);
    float ix1 = fmaxf(ax1, bx1), iy1 = fmaxf(ay1, by1);
    float ix2 = fminf(ax2, bx2), iy2 = fminf(ay2, by2);
    float it = fmaxf(ix2 - ix1, 0.f) * fmaxf(iy2 - iy1, 0.f);
    return it / (aA + aB - it + 1e-9f);
}

extern __shared__ unsigned char dynsmem[];
// layout:
//   sdata : float[10240]  @ 0       (region slice, 40960 B; 10000 used)
//   ckey  : ULL[2048]     @ 40960   (16384 B)
//   skeys : ULL[2048]     @ 57344   (16384 B)
// total 73728 B

__global__ __launch_bounds__(BDIM) void nms_kernel(const float* __restrict__ region,
                                                   const float* __restrict__ neg,
                                                   float* __restrict__ out_tb,
                                                   float* __restrict__ out_k2) {
    float* sdata = (float*)dynsmem;
    unsigned long long* ckey  = (unsigned long long*)(dynsmem + 40960);
    unsigned long long* skeys = (unsigned long long*)(dynsmem + 57344);

    __shared__ int hist[256];
    __shared__ float sneg[MAXD * 5];
    __shared__ int outlist[MAXD];
    __shared__ unsigned int sh_maxbits;
    __shared__ int sh_binthr, sh_total, sh_cnt, sh_found;

    const int t = threadIdx.x;
    const int b = blockIdx.x;
    const int lane = t & 31;
    const float* rb = region + (size_t)b * Nn * 5;

    if (t < 256) hist[t] = 0;
    if (t == 0) sh_maxbits = 0u;

    // ---- coalesced bulk stage: whole region slice (2500 float4) + neg slice ----
    {
        const float4* rb4 = (const float4*)rb;      // b*40000 B offset: 16B aligned
        float4* s4 = (float4*)sdata;
        for (int i = t; i < Nn * 5 / 4; i += BDIM) s4[i] = rb4[i];
        if (t < MAXD * 5) sneg[t] = neg[(size_t)b * MAXD * 5 + t];
    }
    __syncthreads();

    // ---- block max score ----
    unsigned int lm = 0u;
    for (int j = t; j < Nn; j += BDIM) {
        unsigned int sb = __float_as_uint(sdata[j * 5 + 4]);   // scores > 0
        lm = max(lm, sb);
    }
#pragma unroll
    for (int off = 16; off; off >>= 1)
        lm = max(lm, __shfl_xor_sync(0xffffffffu, lm, off));
    if (lane == 0) atomicMax(&sh_maxbits, lm);
    __syncthreads();

    const bool has_conf = __uint_as_float(sh_maxbits) > CONF;
    const float thresh = has_conf ? CONF : 0.0f;
    const int limit = has_conf ? MAXD : TOPK_;

    // ---- histogram of valid scores ----
    for (int j = t; j < Nn; j += BDIM) {
        float sc = sdata[j * 5 + 4];
        if (sc > thresh) {
            int bin = min(max((int)(sc * 256.0f), 0), 255);
            atomicAdd(&hist[bin], 1);
        }
    }
    __syncthreads();

    // ---- candidate selection with escalation fallback ----
    for (int TARGET = 96;; TARGET <<= 2) {
        // warp-parallel suffix scan: lane l covers bins [255-8l .. 248-8l]
        if (t < 32) {
            int base = 255 - lane * 8;
            int s = 0;
#pragma unroll
            for (int i = 0; i < 8; i++) s += hist[base - i];
            int pre = s;
#pragma unroll
            for (int off = 1; off < 32; off <<= 1) {
                int v = __shfl_up_sync(0xffffffffu, pre, off);
                if (lane >= off) pre += v;
            }
            int total = __shfl_sync(0xffffffffu, pre, 31);
            unsigned bal = __ballot_sync(0xffffffffu, pre >= TARGET);
            if (bal) {
                int lw = __ffs(bal) - 1;
                if (lane == lw) {
                    int run = pre - s;
                    int binthr = 0;
#pragma unroll
                    for (int i = 0; i < 8; i++) {
                        run += hist[base - i];
                        if (run >= TARGET) { binthr = base - i; break; }
                    }
                    sh_binthr = binthr;
                }
            } else if (lane == 0) {
                sh_binthr = 0;
            }
            if (lane == 0) { sh_total = total; sh_cnt = 0; sh_found = 0; }
        }
        __syncthreads();
        const int binthr = sh_binthr;

        // compact candidate keys from staged scores
        for (int j = t; j < Nn; j += BDIM) {
            float sc = sdata[j * 5 + 4];
            if (sc > thresh) {
                int bin = min(max((int)(sc * 256.0f), 0), 255);
                if (bin >= binthr) {
                    int pos = atomicAdd(&sh_cnt, 1);
                    ckey[pos] = ((unsigned long long)__float_as_uint(sc) << 32) |
                                (unsigned)(Nn - 1 - j);
                }
            }
        }
        __syncthreads();
        const int C = sh_cnt;

        // rank sort (descending; keys unique -> exact stable order)
        for (int i = t; i < C; i += BDIM) {
            unsigned long long ki = ckey[i];
            int r = 0;
            for (int j = 0; j < C; j++) r += (ckey[j] > ki);
            skeys[r] = ki;
        }
        __syncthreads();

        // ---- single-warp greedy NMS with early exit ----
        if (t < 32) {
            unsigned long long aliveb = 0ull;
            for (int bs = 0; bs < 64 && bs * 32 + lane < C; bs++) aliveb |= (1ull << bs);
            int found = 0;
            for (;;) {
                int myidx = aliveb ? ((__ffsll((long long)aliveb) - 1) * 32 + lane) : INT_MAX;
#pragma unroll
                for (int off = 16; off; off >>= 1)
                    myidx = min(myidx, __shfl_xor_sync(0xffffffffu, myidx, off));
                if (myidx == INT_MAX) break;
                int s = myidx;
                int js = (Nn - 1) - (int)(unsigned)(skeys[s] & 0xffffffffu);
                float x1 = sdata[js * 5 + 0], y1 = sdata[js * 5 + 1];
                float x2 = sdata[js * 5 + 2], y2 = sdata[js * 5 + 3];
                if ((s & 31) == lane) aliveb &= ~(1ull << (s >> 5));
                if ((x2 - x1 >= 1.0f) && (y2 - y1 >= 1.0f)) {
                    if (lane == 0) outlist[found] = s;
                    found++;
                    if (found == limit) break;
                }
                unsigned long long mm = aliveb;
                while (mm) {
                    int b0 = __ffsll((long long)mm) - 1;
                    mm &= mm - 1;
                    int idx = b0 * 32 + lane;
                    int jj = (Nn - 1) - (int)(unsigned)(skeys[idx] & 0xffffffffu);
                    float bx1 = sdata[jj * 5 + 0], by1 = sdata[jj * 5 + 1];
                    float bx2 = sdata[jj * 5 + 2], by2 = sdata[jj * 5 + 3];
                    if (iou_f(x1, y1, x2, y2, bx1, by1, bx2, by2) > IOUT)
                        aliveb &= ~(1ull << b0);
                }
            }
            if (lane == 0) sh_found = found;
        }
        __syncthreads();

        if (sh_found >= limit || sh_cnt >= sh_total || TARGET >= Nn) break;
    }

    // ---- stage 2: 10-box merge + sort + NMS + outputs (shared-only reads) ----
    if (t == 0) {
        int cnt = min(sh_found, limit);
        float cb[MAXD][5];
        for (int k = 0; k < MAXD; k++) {
            if (k < cnt) {
                int s = outlist[k];
                int js = (Nn - 1) - (int)(unsigned)(skeys[s] & 0xffffffffu);
                cb[k][0] = sdata[js * 5 + 0]; cb[k][1] = sdata[js * 5 + 1];
                cb[k][2] = sdata[js * 5 + 2]; cb[k][3] = sdata[js * 5 + 3];
                cb[k][4] = __uint_as_float((unsigned)(skeys[s] >> 32));
            } else {
                for (int c = 0; c < 5; c++) cb[k][c] = sneg[k * 5 + c];
            }
        }
        // stable insertion sort, descending by conf
        for (int i = 1; i < MAXD; i++) {
            float tmp[5];
            for (int c = 0; c < 5; c++) tmp[c] = cb[i][c];
            int j = i - 1;
            while (j >= 0 && cb[j][4] < tmp[4]) {
                for (int c = 0; c < 5; c++) cb[j + 1][c] = cb[j][c];
                j--;
            }
            for (int c = 0; c < 5; c++) cb[j + 1][c] = tmp[c];
        }
        // 10x10 greedy NMS, valid = conf > 0
        bool k2[MAXD];
        for (int i = 0; i < MAXD; i++) k2[i] = cb[i][4] > 0.0f;
        for (int i = 0; i < MAXD; i++) {
            if (!k2[i]) continue;
            for (int jn = i + 1; jn < MAXD; jn++) {
                float io = iou_f(cb[i][0], cb[i][1], cb[i][2], cb[i][3],
                                 cb[jn][0], cb[jn][1], cb[jn][2], cb[jn][3]);
                if (io > IOUT) k2[jn] = false;
            }
        }
        for (int k = 0; k < MAXD; k++) {
            bool kk = k2[k];
            for (int c = 0; c < 4; c++) {
                out_tb[(size_t)b * MAXD * 4 + k * 4 + c] = kk ? cb[k][c] : 0.0f;
                g_bi[b][k][c] = (int)floorf(cb[k][c] + 0.5f);
            }
            out_k2[(size_t)b * MAXD + k] = kk ? 1.0f : 0.0f;
            g_k2[b][k] = kk ? 1 : 0;
        }
    }
}

// Fused render: one block per (image, row). Fast path = pure float4 fill.
__global__ __launch_bounds__(128) void render_kernel(float* __restrict__ out) {
    const int b = blockIdx.y;
    const int y = blockIdx.x;
    const int t = threadIdx.x;
    __shared__ int bx1[MAXD], bx2[MAXD];
    __shared__ unsigned int rowmask;

    if (t < MAXD) {
        bool act = g_k2[b][t] && (y >= g_bi[b][t][1]) && (y < g_bi[b][t][3]);
        bx1[t] = g_bi[b][t][0];
        bx2[t] = g_bi[b][t][2];
        unsigned m = __ballot_sync(0x3ffu, act);
        if (t == 0) rowmask = m;
    }
    __syncthreads();

    unsigned rm = rowmask;
    int xb = t * 4;
    float4 v = make_float4(1.f, 1.f, 1.f, 1.f);
    while (rm) {
        int k = __ffs(rm) - 1;
        rm &= rm - 1;
        int a = bx1[k], c = bx2[k];
        if (xb >= a && xb < c) v.x = 0.f;
        if (xb + 1 >= a && xb + 1 < c) v.y = 0.f;
        if (xb + 2 >= a && xb + 2 < c) v.z = 0.f;
        if (xb + 3 >= a && xb + 3 < c) v.w = 0.f;
    }
    ((float4*)(out + ((size_t)b * Hh + y) * Ww))[t] = v;
}

extern "C" void kernel_launch(void* const* d_in, const int* in_sizes, int n_in,
                              void* d_out, int out_size) {
    // inputs: [0]=x (unused), [1]=region_boxes (B,N,5), [2]=neg_boxes (B,10,5)
    const float* region = (const float*)d_in[1];
    const float* neg = (const float*)d_in[2];
    float* out = (float*)d_out;
    float* out_tb = out + (size_t)Bn * Hh * Ww;          // target_boxes segment
    float* out_k2 = out_tb + (size_t)Bn * MAXD * 4;      // keep2 segment

    const int smem_bytes = 73728;
    cudaFuncSetAttribute(nms_kernel, cudaFuncAttributeMaxDynamicSharedMemorySize, smem_bytes);

    nms_kernel<<<Bn, BDIM, smem_bytes>>>(region, neg, out_tb, out_k2);
    render_kernel<<<dim3(Hh, Bn), 128>>>(out);
}

// round 4
// speedup vs baseline: 1.3427x; 1.3427x over previous
#include <cuda_runtime.h>
#include <cstdint>
#include <climits>

#define BDIM 512
constexpr int Bn = 16, Nn = 2000, Hh = 512, Ww = 512, MAXD = 10, TOPK_ = 5;
constexpr float CONF = 0.2f, IOUT = 0.4f;

// Scratch (device globals, allocation-free)
__device__ int g_bi[Bn][MAXD][4];
__device__ int g_k2[Bn][MAXD];

__device__ __forceinline__ float iou_f(float ax1, float ay1, float ax2, float ay2,
                                       float bx1, float by1, float bx2, float by2) {
    float aA = fmaxf(ax2 - ax1, 0.f) * fmaxf(ay2 - ay1, 0.f);
    float aB = fmaxf(bx2 - bx1, 0.f) * fmaxf(by2 - by1, 0.f);
    float ix1 = fmaxf(ax1, bx1), iy1 = fmaxf(ay1, by1);
    float ix2 = fminf(ax2, bx2), iy2 = fminf(ay2, by2);
    float it = fmaxf(ix2 - ix1, 0.f) * fmaxf(iy2 - iy1, 0.f);
    return it / (aA + aB - it + 1e-9f);
}

extern __shared__ unsigned char dynsmem[];
// layout:
//   sdata : float[10240]  @ 0       (region slice, 40960 B; 10000 used)
//   ckey  : ULL[2048]     @ 40960   (16384 B)
//   skeys : ULL[2048]     @ 57344   (16384 B)
// total 73728 B

__global__ __launch_bounds__(BDIM) void nms_kernel(const float* __restrict__ region,
                                                   const float* __restrict__ neg,
                                                   float* __restrict__ out_tb,
                                                   float* __restrict__ out_k2) {
    float* sdata = (float*)dynsmem;
    unsigned long long* ckey  = (unsigned long long*)(dynsmem + 40960);
    unsigned long long* skeys = (unsigned long long*)(dynsmem + 57344);

    __shared__ int hist[256];
    __shared__ float sneg[MAXD * 5];
    __shared__ float sxb[MAXD][5];
    __shared__ int outlist[MAXD];
    __shared__ unsigned int sh_maxbits;
    __shared__ int sh_binthr, sh_total, sh_cnt, sh_found;

    const int t = threadIdx.x;
    const int b = blockIdx.x;
    const int lane = t & 31;
    const float* rb = region + (size_t)b * Nn * 5;

    if (t < 256) hist[t] = 0;
    if (t == 0) sh_maxbits = 0u;

    // ---- coalesced bulk stage: whole region slice (2500 float4) + neg slice ----
    {
        const float4* rb4 = (const float4*)rb;      // b*40000 B offset: 16B aligned
        float4* s4 = (float4*)sdata;
        for (int i = t; i < Nn * 5 / 4; i += BDIM) s4[i] = rb4[i];
        if (t < MAXD * 5) sneg[t] = neg[(size_t)b * MAXD * 5 + t];
    }
    __syncthreads();

    // ---- block max score ----
    unsigned int lm = 0u;
    for (int j = t; j < Nn; j += BDIM) {
        unsigned int sb = __float_as_uint(sdata[j * 5 + 4]);   // scores > 0
        lm = max(lm, sb);
    }
#pragma unroll
    for (int off = 16; off; off >>= 1)
        lm = max(lm, __shfl_xor_sync(0xffffffffu, lm, off));
    if (lane == 0) atomicMax(&sh_maxbits, lm);
    __syncthreads();

    const bool has_conf = __uint_as_float(sh_maxbits) > CONF;
    const float thresh = has_conf ? CONF : 0.0f;
    const int limit = has_conf ? MAXD : TOPK_;

    // ---- histogram of valid scores ----
    for (int j = t; j < Nn; j += BDIM) {
        float sc = sdata[j * 5 + 4];
        if (sc > thresh) {
            int bin = min(max((int)(sc * 256.0f), 0), 255);
            atomicAdd(&hist[bin], 1);
        }
    }
    __syncthreads();

    // ---- candidate selection with escalation fallback ----
    for (int TARGET = 96;; TARGET <<= 2) {
        // warp-parallel suffix scan: lane l covers bins [255-8l .. 248-8l]
        if (t < 32) {
            int base = 255 - lane * 8;
            int s = 0;
#pragma unroll
            for (int i = 0; i < 8; i++) s += hist[base - i];
            int pre = s;
#pragma unroll
            for (int off = 1; off < 32; off <<= 1) {
                int v = __shfl_up_sync(0xffffffffu, pre, off);
                if (lane >= off) pre += v;
            }
            int total = __shfl_sync(0xffffffffu, pre, 31);
            unsigned bal = __ballot_sync(0xffffffffu, pre >= TARGET);
            if (bal) {
                int lw = __ffs(bal) - 1;
                if (lane == lw) {
                    int run = pre - s;
                    int binthr = 0;
#pragma unroll
                    for (int i = 0; i < 8; i++) {
                        run += hist[base - i];
                        if (run >= TARGET) { binthr = base - i; break; }
                    }
                    sh_binthr = binthr;
                }
            } else if (lane == 0) {
                sh_binthr = 0;
            }
            if (lane == 0) { sh_total = total; sh_cnt = 0; sh_found = 0; }
        }
        __syncthreads();
        const int binthr = sh_binthr;

        // compact candidate keys from staged scores
        for (int j = t; j < Nn; j += BDIM) {
            float sc = sdata[j * 5 + 4];
            if (sc > thresh) {
                int bin = min(max((int)(sc * 256.0f), 0), 255);
                if (bin >= binthr) {
                    int pos = atomicAdd(&sh_cnt, 1);
                    ckey[pos] = ((unsigned long long)__float_as_uint(sc) << 32) |
                                (unsigned)(Nn - 1 - j);
                }
            }
        }
        __syncthreads();
        const int C = sh_cnt;

        // rank sort (descending; keys unique -> exact stable order)
        for (int i = t; i < C; i += BDIM) {
            unsigned long long ki = ckey[i];
            int r = 0;
            for (int j = 0; j < C; j++) r += (ckey[j] > ki);
            skeys[r] = ki;
        }
        __syncthreads();

        // ---- single-warp greedy NMS with early exit ----
        if (t < 32) {
            unsigned long long aliveb = 0ull;
            for (int bs = 0; bs < 64 && bs * 32 + lane < C; bs++) aliveb |= (1ull << bs);
            int found = 0;
            for (;;) {
                int myidx = aliveb ? ((__ffsll((long long)aliveb) - 1) * 32 + lane) : INT_MAX;
#pragma unroll
                for (int off = 16; off; off >>= 1)
                    myidx = min(myidx, __shfl_xor_sync(0xffffffffu, myidx, off));
                if (myidx == INT_MAX) break;
                int s = myidx;
                int js = (Nn - 1) - (int)(unsigned)(skeys[s] & 0xffffffffu);
                float x1 = sdata[js * 5 + 0], y1 = sdata[js * 5 + 1];
                float x2 = sdata[js * 5 + 2], y2 = sdata[js * 5 + 3];
                if ((s & 31) == lane) aliveb &= ~(1ull << (s >> 5));
                if ((x2 - x1 >= 1.0f) && (y2 - y1 >= 1.0f)) {
                    if (lane == 0) outlist[found] = s;
                    found++;
                    if (found == limit) break;
                }
                unsigned long long mm = aliveb;
                while (mm) {
                    int b0 = __ffsll((long long)mm) - 1;
                    mm &= mm - 1;
                    int idx = b0 * 32 + lane;
                    int jj = (Nn - 1) - (int)(unsigned)(skeys[idx] & 0xffffffffu);
                    float bx1 = sdata[jj * 5 + 0], by1 = sdata[jj * 5 + 1];
                    float bx2 = sdata[jj * 5 + 2], by2 = sdata[jj * 5 + 3];
                    if (iou_f(x1, y1, x2, y2, bx1, by1, bx2, by2) > IOUT)
                        aliveb &= ~(1ull << b0);
                }
            }
            if (lane == 0) sh_found = found;
        }
        __syncthreads();

        if (sh_found >= limit || sh_cnt >= sh_total || TARGET >= Nn) break;
    }

    // ---- stage 2: warp-parallel 10-box merge + stable sort + NMS + outputs ----
    if (t < 32) {
        const int cnt = min(sh_found, limit);
        float bx[5];
        bx[0] = bx[1] = bx[2] = bx[3] = 0.f;
        bx[4] = -1.0f;                              // lanes >= MAXD rank last
        if (lane < MAXD) {
            if (lane < cnt) {
                int s = outlist[lane];
                unsigned long long key = skeys[s];
                int js = (Nn - 1) - (int)(unsigned)(key & 0xffffffffu);
                bx[0] = sdata[js * 5 + 0]; bx[1] = sdata[js * 5 + 1];
                bx[2] = sdata[js * 5 + 2]; bx[3] = sdata[js * 5 + 3];
                bx[4] = __uint_as_float((unsigned)(key >> 32));
            } else {
#pragma unroll
                for (int c = 0; c < 5; c++) bx[c] = sneg[lane * 5 + c];
            }
        }
        // stable descending rank by conf (ties -> original slot order)
        int rank = 0;
#pragma unroll
        for (int j = 0; j < MAXD; j++) {
            float cj = __shfl_sync(0xffffffffu, bx[4], j);
            rank += (cj > bx[4]) || (cj == bx[4] && j < lane);
        }
        if (lane < MAXD) {
#pragma unroll
            for (int c = 0; c < 5; c++) sxb[rank][c] = bx[c];
        }
        __syncwarp();
        if (lane < MAXD) {
#pragma unroll
            for (int c = 0; c < 5; c++) bx[c] = sxb[lane][c];
        }
        // greedy 10-step NMS (sequential dependency preserved)
        bool kp = (lane < MAXD) && (bx[4] > 0.0f);
#pragma unroll
        for (int i = 0; i < MAXD; i++) {
            float ax1 = __shfl_sync(0xffffffffu, bx[0], i);
            float ay1 = __shfl_sync(0xffffffffu, bx[1], i);
            float ax2 = __shfl_sync(0xffffffffu, bx[2], i);
            float ay2 = __shfl_sync(0xffffffffu, bx[3], i);
            int ki = __shfl_sync(0xffffffffu, (int)kp, i);
            if (ki && lane > i && kp) {
                if (iou_f(ax1, ay1, ax2, ay2, bx[0], bx[1], bx[2], bx[3]) > IOUT)
                    kp = false;
            }
        }
        if (lane < MAXD) {
#pragma unroll
            for (int c = 0; c < 4; c++) {
                out_tb[(size_t)b * MAXD * 4 + lane * 4 + c] = kp ? bx[c] : 0.0f;
                g_bi[b][lane][c] = (int)floorf(bx[c] + 0.5f);
            }
            out_k2[(size_t)b * MAXD + lane] = kp ? 1.0f : 0.0f;
            g_k2[b][lane] = kp ? 1 : 0;
        }
    }
}

// Fat render: grid (8, Bn); each block renders 64 rows with 512 threads,
// 16 independent coalesced float4 stores per thread.
__global__ __launch_bounds__(512) void render_kernel(float* __restrict__ out) {
    const int b = blockIdx.y;
    const int r0 = blockIdx.x * 64;
    const int t = threadIdx.x;
    __shared__ int sx1[MAXD], sx2[MAXD], sy1[MAXD], sy2[MAXD];
    __shared__ unsigned int rmask[64];

    if (t < MAXD) {
        int kk = g_k2[b][t];
        sx1[t] = g_bi[b][t][0];
        sx2[t] = g_bi[b][t][2];
        sy1[t] = kk ? g_bi[b][t][1] : INT_MAX;
        sy2[t] = kk ? g_bi[b][t][3] : INT_MIN;
    }
    __syncthreads();
    if (t < 64) {
        int y = r0 + t;
        unsigned m = 0;
#pragma unroll
        for (int k = 0; k < MAXD; k++)
            if (y >= sy1[k] && y < sy2[k]) m |= (1u << k);
        rmask[t] = m;
    }
    __syncthreads();

    float4* ob = (float4*)(out + (size_t)b * Hh * Ww) + (size_t)r0 * (Ww / 4);
#pragma unroll
    for (int i = 0; i < 16; i++) {
        int p = t + i * 512;
        int row = p >> 7, ch = p & 127;
        unsigned m = rmask[row];
        float4 v = make_float4(1.f, 1.f, 1.f, 1.f);
        if (m) {
            int xb = ch * 4;
            do {
                int k = __ffs(m) - 1;
                m &= m - 1;
                int a = sx1[k], c = sx2[k];
                if (xb >= a && xb < c) v.x = 0.f;
                if (xb + 1 >= a && xb + 1 < c) v.y = 0.f;
                if (xb + 2 >= a && xb + 2 < c) v.z = 0.f;
                if (xb + 3 >= a && xb + 3 < c) v.w = 0.f;
            } while (m);
        }
        ob[p] = v;
    }
}

extern "C" void kernel_launch(void* const* d_in, const int* in_sizes, int n_in,
                              void* d_out, int out_size) {
    // inputs: [0]=x (unused), [1]=region_boxes (B,N,5), [2]=neg_boxes (B,10,5)
    const float* region = (const float*)d_in[1];
    const float* neg = (const float*)d_in[2];
    float* out = (float*)d_out;
    float* out_tb = out + (size_t)Bn * Hh * Ww;          // target_boxes segment
    float* out_k2 = out_tb + (size_t)Bn * MAXD * 4;      // keep2 segment

    const int smem_bytes = 73728;
    cudaFuncSetAttribute(nms_kernel, cudaFuncAttributeMaxDynamicSharedMemorySize, smem_bytes);

    nms_kernel<<<Bn, BDIM, smem_bytes>>>(region, neg, out_tb, out_k2);
    render_kernel<<<dim3(8, Bn), 512>>>(out);
}

// round 5
// speedup vs baseline: 2.2676x; 1.6888x over previous
#include <cuda_runtime.h>
#include <cstdint>
#include <climits>

#define BDIM 512
constexpr int Bn = 16, Nn = 2000, Hh = 512, Ww = 512, MAXD = 10, TOPK_ = 5;
constexpr float CONF = 0.2f, IOUT = 0.4f;
constexpr int KMAX = 256;
constexpr unsigned FULL = 0xffffffffu;

// Scratch (device globals, allocation-free)
__device__ int g_bi[Bn][MAXD][4];
__device__ int g_k2[Bn][MAXD];

__device__ __forceinline__ float iou_f(float ax1, float ay1, float ax2, float ay2,
                                       float bx1, float by1, float bx2, float by2) {
    float aA = fmaxf(ax2 - ax1, 0.f) * fmaxf(ay2 - ay1, 0.f);
    float aB = fmaxf(bx2 - bx1, 0.f) * fmaxf(by2 - by1, 0.f);
    float ix1 = fmaxf(ax1, bx1), iy1 = fmaxf(ay1, by1);
    float ix2 = fminf(ax2, bx2), iy2 = fminf(ay2, by2);
    float it = fmaxf(ix2 - ix1, 0.f) * fmaxf(iy2 - iy1, 0.f);
    return it / (aA + aB - it + 1e-9f);
}

extern __shared__ unsigned char dynsmem[];
// layout:
//   sscore : float[2048]   @ 0       (8192 B)
//   ckey   : ULL[2048]     @ 8192    (16384 B)
//   skeys  : ULL[2048]     @ 24576   (16384 B)
//   skept  : float4[KMAX]  @ 40960   (4096 B)
// total 45056 B

__global__ __launch_bounds__(BDIM) void nms_kernel(const float* __restrict__ region,
                                                   const float* __restrict__ neg,
                                                   float* __restrict__ out_tb,
                                                   float* __restrict__ out_k2) {
    float* sscore = (float*)dynsmem;
    unsigned long long* ckey  = (unsigned long long*)(dynsmem + 8192);
    unsigned long long* skeys = (unsigned long long*)(dynsmem + 24576);
    float4* skept = (float4*)(dynsmem + 40960);

    __shared__ int hist[256];
    __shared__ float sneg[MAXD * 5];
    __shared__ float okx1[MAXD], oky1[MAXD], okx2[MAXD], oky2[MAXD], oksc[MAXD];
    __shared__ float sxb[MAXD][5];
    __shared__ unsigned int sh_maxbits;
    __shared__ int sh_binthr, sh_cnt, sh_found, sh_exh;

    const int t = threadIdx.x;
    const int b = blockIdx.x;
    const int lane = t & 31;
    const float* rb = region + (size_t)b * Nn * 5;

    if (t < 256) hist[t] = 0;
    if (t == 0) sh_maxbits = 0u;
    __syncthreads();

    // ---- single pass: score stage + max + histogram (bins independent of thresh) ----
    unsigned int lm = 0u;
    for (int j = t; j < Nn; j += BDIM) {
        float sc = __ldg(rb + j * 5 + 4);            // scores > 0
        sscore[j] = sc;
        lm = max(lm, __float_as_uint(sc));
        int bin = min(max((int)(sc * 256.0f), 0), 255);
        atomicAdd(&hist[bin], 1);
    }
#pragma unroll
    for (int off = 16; off; off >>= 1)
        lm = max(lm, __shfl_xor_sync(FULL, lm, off));
    if (lane == 0) atomicMax(&sh_maxbits, lm);
    if (t < MAXD * 5) sneg[t] = neg[(size_t)b * MAXD * 5 + t];
    __syncthreads();

    const bool has_conf = __uint_as_float(sh_maxbits) > CONF;
    const float thresh = has_conf ? CONF : 0.0f;
    const int limit = has_conf ? MAXD : TOPK_;

    // ---- candidate selection with escalation fallback ----
    for (int TARGET = 48;; TARGET <<= 2) {
        // warp-parallel suffix scan over bins (lane l covers [255-8l .. 248-8l])
        if (t < 32) {
            int base = 255 - lane * 8;
            int s = 0;
#pragma unroll
            for (int i = 0; i < 8; i++) s += hist[base - i];
            int pre = s;
#pragma unroll
            for (int off = 1; off < 32; off <<= 1) {
                int v = __shfl_up_sync(FULL, pre, off);
                if (lane >= off) pre += v;
            }
            unsigned bal = __ballot_sync(FULL, pre >= TARGET);
            if (bal) {
                int lw = __ffs(bal) - 1;
                if (lane == lw) {
                    int run = pre - s;
                    int binthr = 0;
#pragma unroll
                    for (int i = 0; i < 8; i++) {
                        run += hist[base - i];
                        if (run >= TARGET) { binthr = base - i; break; }
                    }
                    sh_binthr = binthr;
                }
            } else if (lane == 0) {
                sh_binthr = 0;
            }
            if (lane == 0) { sh_exh = (bal == 0); sh_cnt = 0; sh_found = 0; }
        }
        __syncthreads();
        const int binthr = sh_binthr;

        // compact candidate keys from staged scores
        for (int j = t; j < Nn; j += BDIM) {
            float sc = sscore[j];
            if (sc > thresh) {
                int bin = min(max((int)(sc * 256.0f), 0), 255);
                if (bin >= binthr) {
                    int pos = atomicAdd(&sh_cnt, 1);
                    if (pos < 2048)
                        ckey[pos] = ((unsigned long long)__float_as_uint(sc) << 32) |
                                    (unsigned)(Nn - 1 - j);
                }
            }
        }
        __syncthreads();
        const int C = min(sh_cnt, 2048);

        // rank sort (descending; keys unique -> exact stable order)
        for (int i = t; i < C; i += BDIM) {
            unsigned long long ki = ckey[i];
            int r = 0;
            for (int j = 0; j < C; j++) r += (ckey[j] > ki);
            skeys[r] = ki;
        }
        __syncthreads();

        // ---- single-warp greedy NMS: candidate per lane, suppressor-list check ----
        if (t < 32) {
            int nkept = 0, found = 0;
            for (int c0 = 0; c0 < C; c0 += 32) {
                int ci = c0 + lane;
                bool validl = ci < C;
                float x1 = 0.f, y1 = 0.f, x2 = 0.f, y2 = 0.f, sc = 0.f;
                if (validl) {
                    unsigned long long key = skeys[ci];
                    int js = (Nn - 1) - (int)(unsigned)(key & 0xffffffffu);
                    x1 = __ldg(rb + js * 5 + 0);
                    y1 = __ldg(rb + js * 5 + 1);
                    x2 = __ldg(rb + js * 5 + 2);
                    y2 = __ldg(rb + js * 5 + 3);
                    sc = __uint_as_float((unsigned)(key >> 32));
                }
                bool decided = !validl;
                // pre-kill vs suppressors from earlier chunks
                for (int k = 0; k < nkept; k++) {
                    float4 kb = skept[k];
                    if (!decided && iou_f(kb.x, kb.y, kb.z, kb.w, x1, y1, x2, y2) > IOUT)
                        decided = true;
                }
                bool stop = false;
                for (;;) {
                    unsigned und = __ballot_sync(FULL, !decided);
                    if (!und) break;
                    int i0 = __ffs(und) - 1;
                    float ax1 = __shfl_sync(FULL, x1, i0);
                    float ay1 = __shfl_sync(FULL, y1, i0);
                    float ax2 = __shfl_sync(FULL, x2, i0);
                    float ay2 = __shfl_sync(FULL, y2, i0);
                    if (lane == i0) {
                        skept[nkept] = make_float4(x1, y1, x2, y2);
                        decided = true;
                    }
                    nkept++;
                    bool tiny_ok = (ax2 - ax1 >= 1.0f) && (ay2 - ay1 >= 1.0f);
                    if (tiny_ok) {
                        if (lane == i0) {
                            okx1[found] = x1; oky1[found] = y1;
                            okx2[found] = x2; oky2[found] = y2;
                            oksc[found] = sc;
                        }
                        found++;
                        if (found == limit) { stop = true; break; }
                    }
                    if (!decided &&
                        iou_f(ax1, ay1, ax2, ay2, x1, y1, x2, y2) > IOUT)
                        decided = true;
                    if (nkept == KMAX) { stop = true; break; }
                }
                __syncwarp();
                if (stop) break;
            }
            if (lane == 0) sh_found = found;
        }
        __syncthreads();

        if (sh_found >= limit || sh_exh || TARGET >= Nn) break;
    }

    // ---- stage 2: warp-parallel 10-box merge + stable sort + NMS + outputs ----
    if (t < 32) {
        const int cnt = min(sh_found, limit);
        float bx[5];
        bx[0] = bx[1] = bx[2] = bx[3] = 0.f;
        bx[4] = -1.0f;                              // lanes >= MAXD rank last
        if (lane < MAXD) {
            if (lane < cnt) {
                bx[0] = okx1[lane]; bx[1] = oky1[lane];
                bx[2] = okx2[lane]; bx[3] = oky2[lane];
                bx[4] = oksc[lane];
            } else {
#pragma unroll
                for (int c = 0; c < 5; c++) bx[c] = sneg[lane * 5 + c];
            }
        }
        // stable descending rank by conf (ties -> original slot order)
        int rank = 0;
#pragma unroll
        for (int j = 0; j < MAXD; j++) {
            float cj = __shfl_sync(FULL, bx[4], j);
            rank += (cj > bx[4]) || (cj == bx[4] && j < lane);
        }
        if (lane < MAXD) {
#pragma unroll
            for (int c = 0; c < 5; c++) sxb[rank][c] = bx[c];
        }
        __syncwarp();
        if (lane < MAXD) {
#pragma unroll
            for (int c = 0; c < 5; c++) bx[c] = sxb[lane][c];
        }
        // greedy 10-step NMS (sequential dependency preserved)
        bool kp = (lane < MAXD) && (bx[4] > 0.0f);
#pragma unroll
        for (int i = 0; i < MAXD; i++) {
            float ax1 = __shfl_sync(FULL, bx[0], i);
            float ay1 = __shfl_sync(FULL, bx[1], i);
            float ax2 = __shfl_sync(FULL, bx[2], i);
            float ay2 = __shfl_sync(FULL, bx[3], i);
            int ki = __shfl_sync(FULL, (int)kp, i);
            if (ki && lane > i && kp) {
                if (iou_f(ax1, ay1, ax2, ay2, bx[0], bx[1], bx[2], bx[3]) > IOUT)
                    kp = false;
            }
        }
        if (lane < MAXD) {
#pragma unroll
            for (int c = 0; c < 4; c++) {
                out_tb[(size_t)b * MAXD * 4 + lane * 4 + c] = kp ? bx[c] : 0.0f;
                g_bi[b][lane][c] = (int)floorf(bx[c] + 0.5f);
            }
            out_k2[(size_t)b * MAXD + lane] = kp ? 1.0f : 0.0f;
            g_k2[b][lane] = kp ? 1 : 0;
        }
    }
}

// Render: grid (16, Bn); each block renders 32 rows with 512 threads,
// 8 independent coalesced float4 stores per thread.
__global__ __launch_bounds__(512) void render_kernel(float* __restrict__ out) {
    const int b = blockIdx.y;
    const int r0 = blockIdx.x * 32;
    const int t = threadIdx.x;
    __shared__ int sx1[MAXD], sx2[MAXD], sy1[MAXD], sy2[MAXD];
    __shared__ unsigned int rmask[32];

    if (t < MAXD) {
        int kk = g_k2[b][t];
        sx1[t] = g_bi[b][t][0];
        sx2[t] = g_bi[b][t][2];
        sy1[t] = kk ? g_bi[b][t][1] : INT_MAX;
        sy2[t] = kk ? g_bi[b][t][3] : INT_MIN;
    }
    __syncthreads();
    if (t < 32) {
        int y = r0 + t;
        unsigned m = 0;
#pragma unroll
        for (int k = 0; k < MAXD; k++)
            if (y >= sy1[k] && y < sy2[k]) m |= (1u << k);
        rmask[t] = m;
    }
    __syncthreads();

    float4* ob = (float4*)(out + (size_t)b * Hh * Ww) + (size_t)r0 * (Ww / 4);
#pragma unroll
    for (int i = 0; i < 8; i++) {
        int p = t + i * 512;
        int row = p >> 7, ch = p & 127;
        unsigned m = rmask[row];
        float4 v = make_float4(1.f, 1.f, 1.f, 1.f);
        if (m) {
            int xb = ch * 4;
            do {
                int k = __ffs(m) - 1;
                m &= m - 1;
                int a = sx1[k], c = sx2[k];
                if (xb >= a && xb < c) v.x = 0.f;
                if (xb + 1 >= a && xb + 1 < c) v.y = 0.f;
                if (xb + 2 >= a && xb + 2 < c) v.z = 0.f;
                if (xb + 3 >= a && xb + 3 < c) v.w = 0.f;
            } while (m);
        }
        ob[p] = v;
    }
}

extern "C" void kernel_launch(void* const* d_in, const int* in_sizes, int n_in,
                              void* d_out, int out_size) {
    // inputs: [0]=x (unused), [1]=region_boxes (B,N,5), [2]=neg_boxes (B,10,5)
    const float* region = (const float*)d_in[1];
    const float* neg = (const float*)d_in[2];
    float* out = (float*)d_out;
    float* out_tb = out + (size_t)Bn * Hh * Ww;          // target_boxes segment
    float* out_k2 = out_tb + (size_t)Bn * MAXD * 4;      // keep2 segment

    const int smem_bytes = 45056;
    cudaFuncSetAttribute(nms_kernel, cudaFuncAttributeMaxDynamicSharedMemorySize, smem_bytes);

    nms_kernel<<<Bn, BDIM, smem_bytes>>>(region, neg, out_tb, out_k2);
    render_kernel<<<dim3(16, Bn), 512>>>(out);
}